// round 14
// baseline (speedup 1.0000x reference)
#include <cuda_runtime.h>
#include <cuda_bf16.h>

// ============================================================================
// ArcNegFace fused kernel for GB300 (compute_103 base target)
//   out[b,c] = 64 * ( onehot*a_lb + (1-onehot)*(rw*cos + rw - 1) )
//   cos = normalized feats @ normalized weight^T
//   R14: exact-int8 IMMA path. Normalized values quantized to 16-bit fixed
//        point q=round(x*2^15), split q = h*256 + l (s8 each).
//        q_a*q_b = 2^16 hh + 2^8 (hl+lh) + ll; hh and (hl+lh) accumulated
//        exactly in s32 via mma.m16n8k32.s8; ll dropped (~6e-5 cos rms).
//        Halves MMA count, LDSM count and smem bytes vs bf16 3-term.
// ============================================================================

#define DEVI __device__ __forceinline__

static constexpr int BATCH = 512;
static constexpr int DIM   = 128;
static constexpr int NCLS  = 100000;
static constexpr int TN    = 128;                       // classes per CTA tile
static constexpr int NTILES = (NCLS + TN - 1) / TN;     // 782

// ArcNegFace constants
static constexpr float COSM   = 0.87758256189037271612f;   // cos(0.5)
static constexpr float SINM   = 0.47942553860420300027f;   // sin(0.5)
static constexpr float THRESH = -0.87758256189037271612f;  // cos(pi-0.5)
static constexpr float MMC    = 0.23971276930210150014f;   // sin(pi-0.5)*0.5
static constexpr float EXP2C  = 0.72134752044448170368f;   // 1/(2*ln2)

// smem: s8 tiles, 128B rows + 16B pad = 144B pitch (stride 36 words ->
// 8-row ldmatrix groups hit banks 0,4,...,28: conflict-free)
static constexpr int PITCH   = 144;
static constexpr int TILE_B  = 128 * PITCH;             // 18432
static constexpr int SM_BH  = 0;
static constexpr int SM_BL  = SM_BH + TILE_B;
static constexpr int SM_A0H = SM_BL + TILE_B;
static constexpr int SM_A0L = SM_A0H + TILE_B;
static constexpr int SM_A1H = SM_A0L + TILE_B;
static constexpr int SM_A1L = SM_A1H + TILE_B;
static constexpr int SMEM_BYTES = SM_A1L + TILE_B;      // 110592

// ---------------- device scratch (allocation-free rule) ----------------
__device__ unsigned g_Ah[BATCH * DIM / 4];              // 4x s8 packed (hi)
__device__ unsigned g_Al[BATCH * DIM / 4];              // 4x s8 packed (lo)
__device__ float g_alb[BATCH];
__device__ int   g_lab[BATCH];

// ---------------- helpers ----------------
DEVI unsigned smem_u32(const void* p) {
    unsigned r;
    asm("{ .reg .u64 t; cvta.to.shared.u64 t, %1; cvt.u32.u64 %0, t; }"
        : "=r"(r) : "l"(p));
    return r;
}
DEVI float ex2f(float x) {
    float y;
    asm("ex2.approx.ftz.f32 %0, %1;" : "=f"(y) : "f"(x));
    return y;
}
DEVI void ldm_x4(unsigned* r, unsigned addr) {
    asm volatile("ldmatrix.sync.aligned.m8n8.x4.shared.b16 {%0,%1,%2,%3}, [%4];"
                 : "=r"(r[0]), "=r"(r[1]), "=r"(r[2]), "=r"(r[3]) : "r"(addr));
}
DEVI void mma_s8(int* d, const unsigned* a, unsigned b0, unsigned b1) {
    asm volatile(
        "mma.sync.aligned.m16n8k32.row.col.s32.s8.s8.s32 "
        "{%0,%1,%2,%3}, {%4,%5,%6,%7}, {%8,%9}, {%0,%1,%2,%3};"
        : "+r"(d[0]), "+r"(d[1]), "+r"(d[2]), "+r"(d[3])
        : "r"(a[0]), "r"(a[1]), "r"(a[2]), "r"(a[3]), "r"(b0), "r"(b1));
}
DEVI void cpa16(unsigned dst, const void* src) {
    asm volatile("cp.async.cg.shared.global [%0], [%1], 16;"
                 :: "r"(dst), "l"(src) : "memory");
}
DEVI void cpa_commit() { asm volatile("cp.async.commit_group;" ::: "memory"); }
DEVI void cpa_wait_all() { asm volatile("cp.async.wait_group 0;" ::: "memory"); }
DEVI float rsqrt_ref(float s) {
    float r = rsqrtf(s);
    return r * (1.5f - 0.5f * s * r * r);   // Newton step -> ~fp32 exact
}
// quantize x in (-1,1) to q = h*256 + l (s8 each), q ~= x * 2^15
DEVI void quant2(float x, int& h, int& l) {
    int q = __float2int_rn(x * 32768.0f);
    q = max(-32639, min(32639, q));
    h = (q + 128) >> 8;                 // [-127, 127]
    l = q - (h << 8);                   // [-128, 127]
}
DEVI unsigned packs8(int a, int b, int c, int d) {
    return (unsigned)(a & 0xFF) | ((unsigned)(b & 0xFF) << 8)
         | ((unsigned)(c & 0xFF) << 16) | ((unsigned)(d & 0xFF) << 24);
}
DEVI float anf(float cv, float a, float a64, bool isl) {
    float t  = cv - a;
    float rw = 1.2f * ex2f(-EXP2C * t * t);
    float v  = 64.0f * fmaf(rw, cv + 1.0f, -1.0f);
    return isl ? a64 : v;
}

// ============================================================================
// Prep: normalize feats -> quantized s8 hi/lo globals; a_lb per row.
// ============================================================================
__global__ void prep_kernel(const float* __restrict__ feats,
                            const int* __restrict__ labels,
                            const float* __restrict__ weight) {
    int b = blockIdx.x * (blockDim.x >> 5) + (threadIdx.x >> 5);
    int lane = threadIdx.x & 31;
    if (b >= BATCH) return;

    float4 v = reinterpret_cast<const float4*>(feats)[b * 32 + lane];
    float s = v.x * v.x + v.y * v.y + v.z * v.z + v.w * v.w;
#pragma unroll
    for (int o = 16; o; o >>= 1) s += __shfl_xor_sync(0xffffffffu, s, o);
    float rinv = rsqrt_ref(s);
    float e0 = v.x * rinv, e1 = v.y * rinv, e2 = v.z * rinv, e3 = v.w * rinv;

    int h0, l0, h1, l1, h2, l2, h3, l3;
    quant2(e0, h0, l0); quant2(e1, h1, l1);
    quant2(e2, h2, l2); quant2(e3, h3, l3);
    g_Ah[b * 32 + lane] = packs8(h0, h1, h2, h3);
    g_Al[b * 32 + lane] = packs8(l0, l1, l2, l3);

    int lab = labels[b];
    float4 wv = reinterpret_cast<const float4*>(weight)[(size_t)lab * 32 + lane];
    float sw = wv.x * wv.x + wv.y * wv.y + wv.z * wv.z + wv.w * wv.w;
    float dt = e0 * wv.x + e1 * wv.y + e2 * wv.z + e3 * wv.w;
#pragma unroll
    for (int o = 16; o; o >>= 1) sw += __shfl_xor_sync(0xffffffffu, sw, o);
#pragma unroll
    for (int o = 16; o; o >>= 1) dt += __shfl_xor_sync(0xffffffffu, dt, o);

    if (lane == 0) {
        float rw = rsqrt_ref(sw);
        float c = dt * rw;
        c = fminf(1.0f, fmaxf(-1.0f, c));
        float a = (c > THRESH)
                      ? (c * COSM - SINM * sqrtf(fmaxf(0.0f, 1.0f - c * c)))
                      : (c - MMC);
        g_alb[b] = a;
        g_lab[b] = lab;
    }
}

// ============================================================================
// Main: one CTA (512 thr, 16 warps) per 128-class tile.
// Warp grid 4(m) x 4(n): each warp m32 x n32. 4 M-tiles of 128 rows.
// A tiles double-buffered (cp.async). IMMA m16n8k32.s8, 2 acc sets.
// ============================================================================
extern __shared__ char smem[];

__global__ void __launch_bounds__(512, 1)
arcneg_main(const float* __restrict__ weight, float* __restrict__ out) {
    unsigned sb = smem_u32(smem);
    int tid = threadIdx.x;
    int w = tid >> 5;          // 0..15
    int lane = tid & 31;
    int n0 = blockIdx.x * TN;
    int mw = w >> 2;           // 0..3 : m32 block
    int nw = w & 3;            // 0..3 : n32 block

    const unsigned bufH[2] = {SM_A0H, SM_A1H};
    const unsigned bufL[2] = {SM_A0L, SM_A1L};

    // issue cp.async fill for M-tile 0 into buffer 0 (overlaps B prologue)
    {
        const char* srcH = reinterpret_cast<const char*>(g_Ah);
        const char* srcL = reinterpret_cast<const char*>(g_Al);
#pragma unroll
        for (int j = tid; j < 1024; j += 512) {     // 16B chunks, 8 per row
            int row = j >> 3, cc = j & 7;
            unsigned off = row * PITCH + cc * 16;
            int gsrc = row * 128 + cc * 16;
            cpa16(sb + SM_A0H + off, srcH + gsrc);
            cpa16(sb + SM_A0L + off, srcL + gsrc);
        }
        cpa_commit();
    }

    // ---- Load + normalize + quantize weight tile (128 classes x 128 dims) ----
#pragma unroll 4
    for (int k = 0; k < 8; k++) {
        int r = k * 16 + w;
        int c = n0 + r;
        float4 v = make_float4(0.f, 0.f, 0.f, 0.f);
        if (c < NCLS) v = reinterpret_cast<const float4*>(weight)[(size_t)c * 32 + lane];
        float s = v.x * v.x + v.y * v.y + v.z * v.z + v.w * v.w;
#pragma unroll
        for (int o = 16; o; o >>= 1) s += __shfl_xor_sync(0xffffffffu, s, o);
        float rinv = 0.0f;
        if (c < NCLS && s > 1e-30f) rinv = rsqrt_ref(s);
        int h0, l0, h1, l1, h2, l2, h3, l3;
        quant2(v.x * rinv, h0, l0); quant2(v.y * rinv, h1, l1);
        quant2(v.z * rinv, h2, l2); quant2(v.w * rinv, h3, l3);
        unsigned off = r * PITCH + lane * 4;
        *reinterpret_cast<unsigned*>(smem + SM_BH + off) = packs8(h0, h1, h2, h3);
        *reinterpret_cast<unsigned*>(smem + SM_BL + off) = packs8(l0, l1, l2, l3);
    }

    // ldmatrix per-lane address patterns (s8 pairs viewed as b16 units)
    const unsigned aL = (unsigned)((mw * 32 + (lane & 15)) * PITCH + ((lane & 16) >> 1) * 2);
    const unsigned bL = (unsigned)((nw * 32 + (lane & 7) + ((lane & 16) >> 1)) * PITCH + (lane & 8) * 2);
    const unsigned bbH = sb + SM_BH + bL;
    const unsigned bbL = sb + SM_BL + bL;

    int q = lane >> 2, rr = lane & 3;

#pragma unroll 1
    for (int mt = 0; mt < 4; mt++) {
        cpa_wait_all();        // buffer mt&1 data landed (this thread's copies)
        __syncthreads();       // all copies visible; prior readers done

        // prefetch next M-tile's A into the other buffer (overlaps mainloop)
        if (mt < 3) {
            const char* srcH = reinterpret_cast<const char*>(g_Ah) + (mt + 1) * 16384;
            const char* srcL = reinterpret_cast<const char*>(g_Al) + (mt + 1) * 16384;
            unsigned dH = sb + bufH[(mt + 1) & 1];
            unsigned dL = sb + bufL[(mt + 1) & 1];
#pragma unroll
            for (int j = tid; j < 1024; j += 512) {
                int row = j >> 3, cc = j & 7;
                unsigned off = row * PITCH + cc * 16;
                int gsrc = row * 128 + cc * 16;
                cpa16(dH + off, srcH + gsrc);
                cpa16(dL + off, srcL + gsrc);
            }
        }
        cpa_commit();          // commit (possibly empty) group every mt

        const unsigned abH = sb + bufH[mt & 1] + aL;
        const unsigned abL = sb + bufL[mt & 1] + aL;

        int ahh[2][4][4], ahl[2][4][4];          // acc sets: hh and (hl+lh)
#pragma unroll
        for (int i = 0; i < 2; i++)
#pragma unroll
            for (int j = 0; j < 4; j++)
#pragma unroll
                for (int e = 0; e < 4; e++) { ahh[i][j][e] = 0; ahl[i][j][e] = 0; }

        // ---- mainloop: 4 k32-chunks; per chunk 8 LDSM -> 24 IMMA ----
#pragma unroll
        for (int kc = 0; kc < 4; kc++) {
            unsigned ka = kc * 32;               // 32 s8 = 32 bytes
            unsigned ah[2][4], al[2][4], bh[2][4], bl[2][4];
#pragma unroll
            for (int mi = 0; mi < 2; mi++)
                ldm_x4(ah[mi], abH + mi * (16 * PITCH) + ka);
#pragma unroll
            for (int nj = 0; nj < 2; nj++)
                ldm_x4(bh[nj], bbH + nj * (16 * PITCH) + ka);
#pragma unroll
            for (int mi = 0; mi < 2; mi++)
                ldm_x4(al[mi], abL + mi * (16 * PITCH) + ka);
#pragma unroll
            for (int nj = 0; nj < 2; nj++)
                ldm_x4(bl[nj], bbL + nj * (16 * PITCH) + ka);

            // hh -> ahh
#pragma unroll
            for (int mi = 0; mi < 2; mi++)
#pragma unroll
                for (int ni = 0; ni < 4; ni++)
                    mma_s8(ahh[mi][ni], ah[mi],
                           bh[ni >> 1][(ni & 1) * 2],
                           bh[ni >> 1][(ni & 1) * 2 + 1]);
            // hl -> ahl
#pragma unroll
            for (int mi = 0; mi < 2; mi++)
#pragma unroll
                for (int ni = 0; ni < 4; ni++)
                    mma_s8(ahl[mi][ni], ah[mi],
                           bl[ni >> 1][(ni & 1) * 2],
                           bl[ni >> 1][(ni & 1) * 2 + 1]);
            // lh -> ahl (same 2^8 scale)
#pragma unroll
            for (int mi = 0; mi < 2; mi++)
#pragma unroll
                for (int ni = 0; ni < 4; ni++)
                    mma_s8(ahl[mi][ni], al[mi],
                           bh[ni >> 1][(ni & 1) * 2],
                           bh[ni >> 1][(ni & 1) * 2 + 1]);
        }

        // ---- fused epilogue: cos = hh*2^-14 + (hl+lh)*2^-22 ----
#pragma unroll
        for (int mi = 0; mi < 2; mi++) {
            int r0 = mt * 128 + mw * 32 + mi * 16 + q;
            int r1 = r0 + 8;
            float av0 = g_alb[r0], av1 = g_alb[r1];
            int   lb0 = g_lab[r0], lb1 = g_lab[r1];
            float a64_0 = 64.0f * av0, a64_1 = 64.0f * av1;
#pragma unroll
            for (int ni = 0; ni < 4; ni++) {
                int c = n0 + nw * 32 + ni * 8 + rr * 2;
                if (c < NCLS) {
                    float cv00 = fmaf((float)ahh[mi][ni][0], 0x1p-14f,
                                      (float)ahl[mi][ni][0] * 0x1p-22f);
                    float cv01 = fmaf((float)ahh[mi][ni][1], 0x1p-14f,
                                      (float)ahl[mi][ni][1] * 0x1p-22f);
                    float cv10 = fmaf((float)ahh[mi][ni][2], 0x1p-14f,
                                      (float)ahl[mi][ni][2] * 0x1p-22f);
                    float cv11 = fmaf((float)ahh[mi][ni][3], 0x1p-14f,
                                      (float)ahl[mi][ni][3] * 0x1p-22f);
                    float2 v0, v1;
                    v0.x = anf(cv00, av0, a64_0, c == lb0);
                    v0.y = anf(cv01, av0, a64_0, c + 1 == lb0);
                    v1.x = anf(cv10, av1, a64_1, c == lb1);
                    v1.y = anf(cv11, av1, a64_1, c + 1 == lb1);
                    __stcs(reinterpret_cast<float2*>(out + (size_t)r0 * NCLS + c), v0);
                    __stcs(reinterpret_cast<float2*>(out + (size_t)r1 * NCLS + c), v1);
                }
            }
        }
    }
}

// ============================================================================
extern "C" void kernel_launch(void* const* d_in, const int* in_sizes, int n_in,
                              void* d_out, int out_size) {
    const float* feats = (const float*)d_in[0];
    const int*   labels = (const int*)d_in[1];
    const float* weight = (const float*)d_in[2];
    for (int i = 0; i < n_in; i++) {
        if (in_sizes[i] == BATCH * DIM) feats = (const float*)d_in[i];
        else if (in_sizes[i] == BATCH) labels = (const int*)d_in[i];
        else if (in_sizes[i] == NCLS * DIM) weight = (const float*)d_in[i];
    }
    float* out = (float*)d_out;

    cudaFuncSetAttribute(arcneg_main, cudaFuncAttributeMaxDynamicSharedMemorySize,
                         SMEM_BYTES);

    prep_kernel<<<128, 128>>>(feats, labels, weight);
    arcneg_main<<<NTILES, 512, SMEM_BYTES>>>(weight, out);
}

// round 16
// speedup vs baseline: 3.7935x; 3.7935x over previous
#include <cuda_runtime.h>
#include <cuda_fp16.h>

// ============================================================================
// ArcNegFace fused kernel for GB300 (compute_103 base target -> mma.sync path)
//   out[b,c] = 64 * ( onehot*a_lb + (1-onehot)*(rw*cos + rw - 1) )
//   cos = normalized feats @ normalized weight^T
//   R16: R15 (single-pass fp16 HMMA) with the A-tile prefetch stride fixed:
//        fp16 tile = 128 rows * 256 B = 32768 B (R15 used the int8 16384).
//   Base config = R11: TN=256, 512 thr, warp tile m64xn32, cp.async overlap.
// ============================================================================

#define DEVI __device__ __forceinline__

static constexpr int BATCH = 512;
static constexpr int DIM   = 128;
static constexpr int NCLS  = 100000;
static constexpr int TN    = 256;                       // classes per CTA tile
static constexpr int NTILES = (NCLS + TN - 1) / TN;     // 391

// ArcNegFace constants
static constexpr float COSM   = 0.87758256189037271612f;   // cos(0.5)
static constexpr float SINM   = 0.47942553860420300027f;   // sin(0.5)
static constexpr float THRESH = -0.87758256189037271612f;  // cos(pi-0.5)
static constexpr float MMC    = 0.23971276930210150014f;   // sin(pi-0.5)*0.5
static constexpr float EXP2C  = 0.72134752044448170368f;   // 1/(2*ln2)

// smem: 272B pitch rows (pad-8 halves -> conflict-free ldmatrix)
static constexpr int PITCH    = 272;
static constexpr int B_TILE_B = TN * PITCH;             // 69632
static constexpr int A_TILE_B = 128 * PITCH;            // 34816
static constexpr int SM_B = 0;
static constexpr int SM_A = SM_B + B_TILE_B;
static constexpr int SMEM_BYTES = SM_A + A_TILE_B;      // 104448

static constexpr int A_GTILE = 128 * 256;               // 32768 B per M-tile

// ---------------- device scratch (allocation-free rule) ----------------
__device__ unsigned long long g_A[BATCH * DIM / 4];     // 4x fp16 packed
__device__ float g_alb[BATCH];
__device__ int   g_lab[BATCH];

// ---------------- helpers ----------------
DEVI unsigned smem_u32(const void* p) {
    unsigned r;
    asm("{ .reg .u64 t; cvta.to.shared.u64 t, %1; cvt.u32.u64 %0, t; }"
        : "=r"(r) : "l"(p));
    return r;
}
DEVI float ex2f(float x) {
    float y;
    asm("ex2.approx.ftz.f32 %0, %1;" : "=f"(y) : "f"(x));
    return y;
}
DEVI void ldm_x4(unsigned* r, unsigned addr) {
    asm volatile("ldmatrix.sync.aligned.m8n8.x4.shared.b16 {%0,%1,%2,%3}, [%4];"
                 : "=r"(r[0]), "=r"(r[1]), "=r"(r[2]), "=r"(r[3]) : "r"(addr));
}
DEVI void mma_f16(float* d, const unsigned* a, unsigned b0, unsigned b1) {
    asm volatile(
        "mma.sync.aligned.m16n8k16.row.col.f32.f16.f16.f32 "
        "{%0,%1,%2,%3}, {%4,%5,%6,%7}, {%8,%9}, {%0,%1,%2,%3};"
        : "+f"(d[0]), "+f"(d[1]), "+f"(d[2]), "+f"(d[3])
        : "r"(a[0]), "r"(a[1]), "r"(a[2]), "r"(a[3]), "r"(b0), "r"(b1));
}
DEVI void cpa16(unsigned dst, const void* src) {
    asm volatile("cp.async.cg.shared.global [%0], [%1], 16;"
                 :: "r"(dst), "l"(src) : "memory");
}
DEVI void cpa_commit() { asm volatile("cp.async.commit_group;" ::: "memory"); }
DEVI void cpa_wait_all() { asm volatile("cp.async.wait_group 0;" ::: "memory"); }
DEVI unsigned long long pack4h(__half a, __half b, __half c, __half d) {
    return (unsigned long long)__half_as_ushort(a)
         | ((unsigned long long)__half_as_ushort(b) << 16)
         | ((unsigned long long)__half_as_ushort(c) << 32)
         | ((unsigned long long)__half_as_ushort(d) << 48);
}
DEVI float rsqrt_ref(float s) {
    float r = rsqrtf(s);
    return r * (1.5f - 0.5f * s * r * r);   // Newton step -> ~fp32 exact
}
DEVI float anf(float cv, float a, float a64, bool isl) {
    float t  = cv - a;
    float rw = 1.2f * ex2f(-EXP2C * t * t);
    float v  = 64.0f * fmaf(rw, cv + 1.0f, -1.0f);
    return isl ? a64 : v;
}

// ============================================================================
// Prep: normalize feats -> fp16 globals; a_lb per row (fp32 exact).
// ============================================================================
__global__ void prep_kernel(const float* __restrict__ feats,
                            const int* __restrict__ labels,
                            const float* __restrict__ weight) {
    int b = blockIdx.x * (blockDim.x >> 5) + (threadIdx.x >> 5);
    int lane = threadIdx.x & 31;
    if (b >= BATCH) return;

    float4 v = reinterpret_cast<const float4*>(feats)[b * 32 + lane];
    float s = v.x * v.x + v.y * v.y + v.z * v.z + v.w * v.w;
#pragma unroll
    for (int o = 16; o; o >>= 1) s += __shfl_xor_sync(0xffffffffu, s, o);
    float rinv = rsqrt_ref(s);
    float e0 = v.x * rinv, e1 = v.y * rinv, e2 = v.z * rinv, e3 = v.w * rinv;

    g_A[b * 32 + lane] = pack4h(__float2half_rn(e0), __float2half_rn(e1),
                                __float2half_rn(e2), __float2half_rn(e3));

    int lab = labels[b];
    float4 wv = reinterpret_cast<const float4*>(weight)[(size_t)lab * 32 + lane];
    float sw = wv.x * wv.x + wv.y * wv.y + wv.z * wv.z + wv.w * wv.w;
    float dt = e0 * wv.x + e1 * wv.y + e2 * wv.z + e3 * wv.w;
#pragma unroll
    for (int o = 16; o; o >>= 1) sw += __shfl_xor_sync(0xffffffffu, sw, o);
#pragma unroll
    for (int o = 16; o; o >>= 1) dt += __shfl_xor_sync(0xffffffffu, dt, o);

    if (lane == 0) {
        float rw = rsqrt_ref(sw);
        float c = dt * rw;
        c = fminf(1.0f, fmaxf(-1.0f, c));
        float a = (c > THRESH)
                      ? (c * COSM - SINM * sqrtf(fmaxf(0.0f, 1.0f - c * c)))
                      : (c - MMC);
        g_alb[b] = a;
        g_lab[b] = lab;
    }
}

// ============================================================================
// Main: one CTA (512 thr, 16 warps) per 256-class tile.
// Warp grid 2(m) x 8(n): each warp m64 x n32. 4 M-tiles of 128 rows.
// Single A buffer, cp.async-filled one M-tile ahead (overlaps epilogue).
// ============================================================================
extern __shared__ char smem[];

__global__ void __launch_bounds__(512, 1)
arcneg_main(const float* __restrict__ weight, float* __restrict__ out) {
    unsigned sb = smem_u32(smem);
    int tid = threadIdx.x;
    int w = tid >> 5;          // 0..15
    int lane = tid & 31;
    int n0 = blockIdx.x * TN;
    int mw = w >> 3;           // 0..1 : m64 block
    int nw = w & 7;            // 0..7 : n32 block

    // issue cp.async fill for M-tile 0 (overlaps B prologue)
    {
        const char* src = reinterpret_cast<const char*>(g_A);
#pragma unroll
        for (int j = tid; j < 2048; j += 512) {     // 16B chunks, 16 per row
            int row = j >> 4, cc = j & 15;
            cpa16(sb + SM_A + row * PITCH + cc * 16, src + row * 256 + cc * 16);
        }
        cpa_commit();
    }

    // ---- Load + normalize weight tile (256 classes x 128 dims) -> fp16 ----
#pragma unroll 4
    for (int k = 0; k < 16; k++) {
        int r = k * 16 + w;
        int c = n0 + r;
        float4 v = make_float4(0.f, 0.f, 0.f, 0.f);
        if (c < NCLS) v = reinterpret_cast<const float4*>(weight)[(size_t)c * 32 + lane];
        float s = v.x * v.x + v.y * v.y + v.z * v.z + v.w * v.w;
#pragma unroll
        for (int o = 16; o; o >>= 1) s += __shfl_xor_sync(0xffffffffu, s, o);
        float rinv = 0.0f;
        if (c < NCLS && s > 1e-30f) rinv = rsqrt_ref(s);
        unsigned off = r * PITCH + lane * 8;
        *reinterpret_cast<unsigned long long*>(smem + SM_B + off) =
            pack4h(__float2half_rn(v.x * rinv), __float2half_rn(v.y * rinv),
                   __float2half_rn(v.z * rinv), __float2half_rn(v.w * rinv));
    }
    cpa_wait_all();
    __syncthreads();           // B visible + A(0) landed

    // ldmatrix per-lane address patterns (within-tile byte offsets)
    const unsigned aL = (unsigned)((mw * 64 + (lane & 15)) * PITCH + ((lane & 16) >> 1) * 2);
    const unsigned bL = (unsigned)((nw * 32 + (lane & 7) + ((lane & 16) >> 1)) * PITCH + (lane & 8) * 2);

    const unsigned ab = sb + SM_A + aL;
    const unsigned bb = sb + SM_B + bL;

    int q = lane >> 2, rr = lane & 3;

#pragma unroll 1
    for (int mt = 0; mt < 4; mt++) {
        float acc[4][4][4];
#pragma unroll
        for (int i = 0; i < 4; i++)
#pragma unroll
            for (int j = 0; j < 4; j++)
#pragma unroll
                for (int e = 0; e < 4; e++) acc[i][j][e] = 0.0f;

        // ---- mainloop: per k-step 6 LDSM -> 16 HMMA ----
#pragma unroll
        for (int k8 = 0; k8 < 8; k8++) {
            unsigned ka = k8 * 32;              // 16 halves = 32 bytes
            unsigned af[4][4], bf[2][4];
#pragma unroll
            for (int mi = 0; mi < 4; mi++)
                ldm_x4(af[mi], ab + mi * (16 * PITCH) + ka);
#pragma unroll
            for (int nj = 0; nj < 2; nj++)
                ldm_x4(bf[nj], bb + nj * (16 * PITCH) + ka);
#pragma unroll
            for (int mi = 0; mi < 4; mi++)
#pragma unroll
                for (int ni = 0; ni < 4; ni++)
                    mma_f16(acc[mi][ni], af[mi],
                            bf[ni >> 1][(ni & 1) * 2],
                            bf[ni >> 1][(ni & 1) * 2 + 1]);
        }
        __syncthreads();       // all warps done reading A(mt)

        // prefetch next M-tile's A (overlaps epilogue below)
        if (mt < 3) {
            const char* src = reinterpret_cast<const char*>(g_A)
                            + (size_t)(mt + 1) * A_GTILE;       // 32768 B/tile
#pragma unroll
            for (int j = tid; j < 2048; j += 512) {
                int row = j >> 4, cc = j & 15;
                cpa16(sb + SM_A + row * PITCH + cc * 16, src + row * 256 + cc * 16);
            }
        }
        cpa_commit();

        // ---- fused epilogue, direct streaming v2 stores ----
#pragma unroll
        for (int mi = 0; mi < 4; mi++) {
            int r0 = mt * 128 + mw * 64 + mi * 16 + q;
            int r1 = r0 + 8;
            float av0 = g_alb[r0], av1 = g_alb[r1];
            int   lb0 = g_lab[r0], lb1 = g_lab[r1];
            float a64_0 = 64.0f * av0, a64_1 = 64.0f * av1;
#pragma unroll
            for (int ni = 0; ni < 4; ni++) {
                int c = n0 + nw * 32 + ni * 8 + rr * 2;
                if (c < NCLS) {
                    float2 v0, v1;
                    v0.x = anf(acc[mi][ni][0], av0, a64_0, c == lb0);
                    v0.y = anf(acc[mi][ni][1], av0, a64_0, c + 1 == lb0);
                    v1.x = anf(acc[mi][ni][2], av1, a64_1, c == lb1);
                    v1.y = anf(acc[mi][ni][3], av1, a64_1, c + 1 == lb1);
                    __stcs(reinterpret_cast<float2*>(out + (size_t)r0 * NCLS + c), v0);
                    __stcs(reinterpret_cast<float2*>(out + (size_t)r1 * NCLS + c), v1);
                }
            }
        }

        if (mt < 3) {
            cpa_wait_all();    // A(mt+1) landed (fills overlapped the epilogue)
            __syncthreads();
        }
    }
}

// ============================================================================
extern "C" void kernel_launch(void* const* d_in, const int* in_sizes, int n_in,
                              void* d_out, int out_size) {
    const float* feats = (const float*)d_in[0];
    const int*   labels = (const int*)d_in[1];
    const float* weight = (const float*)d_in[2];
    for (int i = 0; i < n_in; i++) {
        if (in_sizes[i] == BATCH * DIM) feats = (const float*)d_in[i];
        else if (in_sizes[i] == BATCH) labels = (const int*)d_in[i];
        else if (in_sizes[i] == NCLS * DIM) weight = (const float*)d_in[i];
    }
    float* out = (float*)d_out;

    cudaFuncSetAttribute(arcneg_main, cudaFuncAttributeMaxDynamicSharedMemorySize,
                         SMEM_BYTES);

    prep_kernel<<<128, 128>>>(feats, labels, weight);
    arcneg_main<<<NTILES, 512, SMEM_BYTES>>>(weight, out);
}

// round 17
// speedup vs baseline: 3.8520x; 1.0154x over previous
#include <cuda_runtime.h>
#include <cuda_fp16.h>

// ============================================================================
// ArcNegFace fused kernel for GB300 (compute_103 base target -> mma.sync path)
//   out[b,c] = 64 * ( onehot*a_lb + (1-onehot)*(rw*cos + rw - 1) )
//   cos = normalized feats @ normalized weight^T
//   R17: FULL A matrix (512 rows) resident in smem -> single __syncthreads
//        for the whole kernel; warps free-run through all 4 M-chunks
//        (mainloop + epilogue) so pipe usage self-smooths across warps.
//   fp16 single-pass HMMA (R16), TN=256, 512 thr, warp tile m64xn32.
// ============================================================================

#define DEVI __device__ __forceinline__

static constexpr int BATCH = 512;
static constexpr int DIM   = 128;
static constexpr int NCLS  = 100000;
static constexpr int TN    = 256;                       // classes per CTA tile
static constexpr int NTILES = (NCLS + TN - 1) / TN;     // 391

// ArcNegFace constants
static constexpr float COSM   = 0.87758256189037271612f;   // cos(0.5)
static constexpr float SINM   = 0.47942553860420300027f;   // sin(0.5)
static constexpr float THRESH = -0.87758256189037271612f;  // cos(pi-0.5)
static constexpr float MMC    = 0.23971276930210150014f;   // sin(pi-0.5)*0.5
static constexpr float EXP2C  = 0.72134752044448170368f;   // 1/(2*ln2)

// smem: 272B pitch rows (pad-8 halves -> conflict-free ldmatrix)
static constexpr int PITCH    = 272;
static constexpr int B_TILE_B = TN * PITCH;             // 69632
static constexpr int A_FULL_B = BATCH * PITCH;          // 139264 (all 512 rows)
static constexpr int SM_B = 0;
static constexpr int SM_A = SM_B + B_TILE_B;
static constexpr int SMEM_BYTES = SM_A + A_FULL_B;      // 208896

// ---------------- device scratch (allocation-free rule) ----------------
__device__ unsigned long long g_A[BATCH * DIM / 4];     // 4x fp16 packed
__device__ float g_alb[BATCH];
__device__ int   g_lab[BATCH];

// ---------------- helpers ----------------
DEVI unsigned smem_u32(const void* p) {
    unsigned r;
    asm("{ .reg .u64 t; cvta.to.shared.u64 t, %1; cvt.u32.u64 %0, t; }"
        : "=r"(r) : "l"(p));
    return r;
}
DEVI float ex2f(float x) {
    float y;
    asm("ex2.approx.ftz.f32 %0, %1;" : "=f"(y) : "f"(x));
    return y;
}
DEVI void ldm_x4(unsigned* r, unsigned addr) {
    asm volatile("ldmatrix.sync.aligned.m8n8.x4.shared.b16 {%0,%1,%2,%3}, [%4];"
                 : "=r"(r[0]), "=r"(r[1]), "=r"(r[2]), "=r"(r[3]) : "r"(addr));
}
DEVI void mma_f16(float* d, const unsigned* a, unsigned b0, unsigned b1) {
    asm volatile(
        "mma.sync.aligned.m16n8k16.row.col.f32.f16.f16.f32 "
        "{%0,%1,%2,%3}, {%4,%5,%6,%7}, {%8,%9}, {%0,%1,%2,%3};"
        : "+f"(d[0]), "+f"(d[1]), "+f"(d[2]), "+f"(d[3])
        : "r"(a[0]), "r"(a[1]), "r"(a[2]), "r"(a[3]), "r"(b0), "r"(b1));
}
DEVI void cpa16(unsigned dst, const void* src) {
    asm volatile("cp.async.cg.shared.global [%0], [%1], 16;"
                 :: "r"(dst), "l"(src) : "memory");
}
DEVI void cpa_commit() { asm volatile("cp.async.commit_group;" ::: "memory"); }
DEVI void cpa_wait_all() { asm volatile("cp.async.wait_group 0;" ::: "memory"); }
DEVI unsigned long long pack4h(__half a, __half b, __half c, __half d) {
    return (unsigned long long)__half_as_ushort(a)
         | ((unsigned long long)__half_as_ushort(b) << 16)
         | ((unsigned long long)__half_as_ushort(c) << 32)
         | ((unsigned long long)__half_as_ushort(d) << 48);
}
DEVI float rsqrt_ref(float s) {
    float r = rsqrtf(s);
    return r * (1.5f - 0.5f * s * r * r);   // Newton step -> ~fp32 exact
}
DEVI float anf(float cv, float a, float a64, bool isl) {
    float t  = cv - a;
    float rw = 1.2f * ex2f(-EXP2C * t * t);
    float v  = 64.0f * fmaf(rw, cv + 1.0f, -1.0f);
    return isl ? a64 : v;
}

// ============================================================================
// Prep: normalize feats -> fp16 globals; a_lb per row (fp32 exact).
// ============================================================================
__global__ void prep_kernel(const float* __restrict__ feats,
                            const int* __restrict__ labels,
                            const float* __restrict__ weight) {
    int b = blockIdx.x * (blockDim.x >> 5) + (threadIdx.x >> 5);
    int lane = threadIdx.x & 31;
    if (b >= BATCH) return;

    float4 v = reinterpret_cast<const float4*>(feats)[b * 32 + lane];
    float s = v.x * v.x + v.y * v.y + v.z * v.z + v.w * v.w;
#pragma unroll
    for (int o = 16; o; o >>= 1) s += __shfl_xor_sync(0xffffffffu, s, o);
    float rinv = rsqrt_ref(s);
    float e0 = v.x * rinv, e1 = v.y * rinv, e2 = v.z * rinv, e3 = v.w * rinv;

    g_A[b * 32 + lane] = pack4h(__float2half_rn(e0), __float2half_rn(e1),
                                __float2half_rn(e2), __float2half_rn(e3));

    int lab = labels[b];
    float4 wv = reinterpret_cast<const float4*>(weight)[(size_t)lab * 32 + lane];
    float sw = wv.x * wv.x + wv.y * wv.y + wv.z * wv.z + wv.w * wv.w;
    float dt = e0 * wv.x + e1 * wv.y + e2 * wv.z + e3 * wv.w;
#pragma unroll
    for (int o = 16; o; o >>= 1) sw += __shfl_xor_sync(0xffffffffu, sw, o);
#pragma unroll
    for (int o = 16; o; o >>= 1) dt += __shfl_xor_sync(0xffffffffu, dt, o);

    if (lane == 0) {
        float rw = rsqrt_ref(sw);
        float c = dt * rw;
        c = fminf(1.0f, fmaxf(-1.0f, c));
        float a = (c > THRESH)
                      ? (c * COSM - SINM * sqrtf(fmaxf(0.0f, 1.0f - c * c)))
                      : (c - MMC);
        g_alb[b] = a;
        g_lab[b] = lab;
    }
}

// ============================================================================
// Main: one CTA (512 thr, 16 warps) per 256-class tile.
// Warp grid 2(m) x 8(n): each warp m64 x n32; 4 M-chunks of 128 rows.
// Full A resident in smem; ONE block barrier total; warps free-run.
// ============================================================================
extern __shared__ char smem[];

__global__ void __launch_bounds__(512, 1)
arcneg_main(const float* __restrict__ weight, float* __restrict__ out) {
    unsigned sb = smem_u32(smem);
    int tid = threadIdx.x;
    int w = tid >> 5;          // 0..15
    int lane = tid & 31;
    int n0 = blockIdx.x * TN;
    int mw = w >> 3;           // 0..1 : m64 block
    int nw = w & 7;            // 0..7 : n32 block

    // issue cp.async fill for ALL of A (overlaps B prologue)
    {
        const char* src = reinterpret_cast<const char*>(g_A);
#pragma unroll
        for (int j = tid; j < 8192; j += 512) {     // 16B chunks, 16 per row
            int row = j >> 4, cc = j & 15;
            cpa16(sb + SM_A + row * PITCH + cc * 16, src + row * 256 + cc * 16);
        }
        cpa_commit();
    }

    // ---- Load + normalize weight tile (256 classes x 128 dims) -> fp16 ----
#pragma unroll 4
    for (int k = 0; k < 16; k++) {
        int r = k * 16 + w;
        int c = n0 + r;
        float4 v = make_float4(0.f, 0.f, 0.f, 0.f);
        if (c < NCLS) v = reinterpret_cast<const float4*>(weight)[(size_t)c * 32 + lane];
        float s = v.x * v.x + v.y * v.y + v.z * v.z + v.w * v.w;
#pragma unroll
        for (int o = 16; o; o >>= 1) s += __shfl_xor_sync(0xffffffffu, s, o);
        float rinv = 0.0f;
        if (c < NCLS && s > 1e-30f) rinv = rsqrt_ref(s);
        unsigned off = r * PITCH + lane * 8;
        *reinterpret_cast<unsigned long long*>(smem + SM_B + off) =
            pack4h(__float2half_rn(v.x * rinv), __float2half_rn(v.y * rinv),
                   __float2half_rn(v.z * rinv), __float2half_rn(v.w * rinv));
    }
    cpa_wait_all();
    __syncthreads();           // THE only block barrier: B + full A visible

    // ldmatrix per-lane address patterns (within-tile byte offsets)
    const unsigned aL = (unsigned)((mw * 64 + (lane & 15)) * PITCH + ((lane & 16) >> 1) * 2);
    const unsigned bL = (unsigned)((nw * 32 + (lane & 7) + ((lane & 16) >> 1)) * PITCH + (lane & 8) * 2);

    const unsigned bb = sb + SM_B + bL;
    int q = lane >> 2, rr = lane & 3;

#pragma unroll 1
    for (int mt = 0; mt < 4; mt++) {
        const unsigned ab = sb + SM_A + (unsigned)(mt * 128 * PITCH) + aL;

        float acc[4][4][4];
#pragma unroll
        for (int i = 0; i < 4; i++)
#pragma unroll
            for (int j = 0; j < 4; j++)
#pragma unroll
                for (int e = 0; e < 4; e++) acc[i][j][e] = 0.0f;

        // ---- mainloop: per k-step 6 LDSM -> 16 HMMA ----
#pragma unroll
        for (int k8 = 0; k8 < 8; k8++) {
            unsigned ka = k8 * 32;              // 16 halves = 32 bytes
            unsigned af[4][4], bf[2][4];
#pragma unroll
            for (int mi = 0; mi < 4; mi++)
                ldm_x4(af[mi], ab + mi * (16 * PITCH) + ka);
#pragma unroll
            for (int nj = 0; nj < 2; nj++)
                ldm_x4(bf[nj], bb + nj * (16 * PITCH) + ka);
#pragma unroll
            for (int mi = 0; mi < 4; mi++)
#pragma unroll
                for (int ni = 0; ni < 4; ni++)
                    mma_f16(acc[mi][ni], af[mi],
                            bf[ni >> 1][(ni & 1) * 2],
                            bf[ni >> 1][(ni & 1) * 2 + 1]);
        }

        // ---- fused epilogue, direct streaming v2 stores (no syncs) ----
#pragma unroll
        for (int mi = 0; mi < 4; mi++) {
            int r0 = mt * 128 + mw * 64 + mi * 16 + q;
            int r1 = r0 + 8;
            float av0 = g_alb[r0], av1 = g_alb[r1];
            int   lb0 = g_lab[r0], lb1 = g_lab[r1];
            float a64_0 = 64.0f * av0, a64_1 = 64.0f * av1;
#pragma unroll
            for (int ni = 0; ni < 4; ni++) {
                int c = n0 + nw * 32 + ni * 8 + rr * 2;
                if (c < NCLS) {
                    float2 v0, v1;
                    v0.x = anf(acc[mi][ni][0], av0, a64_0, c == lb0);
                    v0.y = anf(acc[mi][ni][1], av0, a64_0, c + 1 == lb0);
                    v1.x = anf(acc[mi][ni][2], av1, a64_1, c == lb1);
                    v1.y = anf(acc[mi][ni][3], av1, a64_1, c + 1 == lb1);
                    __stcs(reinterpret_cast<float2*>(out + (size_t)r0 * NCLS + c), v0);
                    __stcs(reinterpret_cast<float2*>(out + (size_t)r1 * NCLS + c), v1);
                }
            }
        }
    }
}

// ============================================================================
extern "C" void kernel_launch(void* const* d_in, const int* in_sizes, int n_in,
                              void* d_out, int out_size) {
    const float* feats = (const float*)d_in[0];
    const int*   labels = (const int*)d_in[1];
    const float* weight = (const float*)d_in[2];
    for (int i = 0; i < n_in; i++) {
        if (in_sizes[i] == BATCH * DIM) feats = (const float*)d_in[i];
        else if (in_sizes[i] == BATCH) labels = (const int*)d_in[i];
        else if (in_sizes[i] == NCLS * DIM) weight = (const float*)d_in[i];
    }
    float* out = (float*)d_out;

    cudaFuncSetAttribute(arcneg_main, cudaFuncAttributeMaxDynamicSharedMemorySize,
                         SMEM_BYTES);

    prep_kernel<<<128, 128>>>(feats, labels, weight);
    arcneg_main<<<NTILES, 512, SMEM_BYTES>>>(weight, out);
}